// round 5
// baseline (speedup 1.0000x reference)
#include <cuda_runtime.h>
#include <cuda_bf16.h>
#include <cstdint>

// Off-diagonal Gram sum via:
//   (1/D) sum_d [ (sum_b x2[b,d])^2 - sum_b x2[b,d]^2 ],  x2 = x*x.
//
// R5: LDG path capped at ~2.2 TB/s regardless of MLP/occupancy (R2-R4),
// so switch the load path to bulk-async (TMA) copies into shared memory.
// Each CTA owns a 256-float d-chunk; one thread issues 32 x 1KB
// cp.async.bulk (one per b row segment) completing on one mbarrier.
// Compute reads the [32][256] smem tile conflict-free.

#define B_ROWS  32
#define CHUNK_D 256                      // floats per CTA chunk
#define THREADS 256
#define CHUNK_BYTES (CHUNK_D * 4)        // 1024 B per b-row segment
#define TILE_BYTES  (B_ROWS * CHUNK_BYTES)  // 32 KB

__device__ double g_acc = 0.0;
__device__ unsigned int g_count = 0;

__device__ __forceinline__ uint32_t smem_u32(const void* p) {
    uint32_t a;
    asm("{ .reg .u64 t; cvta.to.shared.u64 t, %1; cvt.u32.u64 %0, t; }"
        : "=r"(a) : "l"(p));
    return a;
}

__global__ void __launch_bounds__(THREADS, 4)
ortho_tma_kernel(const float* __restrict__ in,
                 float* __restrict__ out,
                 int D, double inv_d) {
    __shared__ __align__(128) float tile[B_ROWS][CHUNK_D];
    __shared__ __align__(8) unsigned long long mbar;

    const int tid = threadIdx.x;
    const uint32_t mbar_a = smem_u32(&mbar);

    if (tid == 0) {
        // arrive count = 1 (the issuing thread's arrive.expect_tx)
        asm volatile("mbarrier.init.shared.b64 [%0], %1;"
                     :: "r"(mbar_a), "r"(1u) : "memory");
    }
    __syncthreads();

    if (tid == 0) {
        asm volatile("mbarrier.arrive.expect_tx.shared.b64 _, [%0], %1;"
                     :: "r"(mbar_a), "r"((uint32_t)TILE_BYTES) : "memory");
        const float* src = in + (size_t)blockIdx.x * CHUNK_D;
        uint32_t dst = smem_u32(&tile[0][0]);
        #pragma unroll
        for (int b = 0; b < B_ROWS; b++) {
            asm volatile(
                "cp.async.bulk.shared::cta.global.mbarrier::complete_tx::bytes "
                "[%0], [%1], %2, [%3];"
                :: "r"(dst + b * CHUNK_BYTES),
                   "l"(src + (size_t)b * D),
                   "r"((uint32_t)CHUNK_BYTES),
                   "r"(mbar_a)
                : "memory");
        }
    }

    // wait for all 32 segments (phase 0)
    {
        uint32_t done;
        asm volatile(
            "{\n\t"
            ".reg .pred p;\n\t"
            "mbarrier.try_wait.parity.acquire.cta.shared::cta.b64 p, [%1], %2;\n\t"
            "selp.b32 %0, 1, 0, p;\n\t"
            "}"
            : "=r"(done) : "r"(mbar_a), "r"(0u) : "memory");
        if (!done) {
            asm volatile(
                "{\n\t"
                ".reg .pred P1;\n\t"
                "WL_%=:\n\t"
                "mbarrier.try_wait.parity.acquire.cta.shared::cta.b64 P1, [%0], %1, 0x989680;\n\t"
                "@P1 bra.uni WD_%=;\n\t"
                "bra.uni WL_%=;\n\t"
                "WD_%=:\n\t"
                "}"
                :: "r"(mbar_a), "r"(0u) : "memory");
        }
    }

    // thread t owns column d = t: s = sum_b x^2, tt = sum_b x^4
    float s = 0.f, tt = 0.f;
    #pragma unroll
    for (int b = 0; b < B_ROWS; b++) {
        float x = tile[b][tid];
        float a = x * x;
        s += a;
        tt = fmaf(a, a, tt);
    }
    double contrib = (double)(s * s - tt);

    // warp reduction (doubles)
    #pragma unroll
    for (int off = 16; off > 0; off >>= 1)
        contrib += __shfl_down_sync(0xFFFFFFFFu, contrib, off);

    __shared__ double warp_sums[THREADS / 32];
    int lane = tid & 31;
    int wid  = tid >> 5;
    if (lane == 0) warp_sums[wid] = contrib;
    __syncthreads();

    if (tid == 0) {
        double blk = 0.0;
        #pragma unroll
        for (int w = 0; w < THREADS / 32; w++) blk += warp_sums[w];
        atomicAdd(&g_acc, blk);
        __threadfence();
        unsigned int ticket = atomicAdd(&g_count, 1u);
        if (ticket == gridDim.x - 1) {
            out[0] = (float)(g_acc * inv_d);
            g_acc = 0.0;     // reset for next graph replay
            g_count = 0u;
        }
    }
}

extern "C" void kernel_launch(void* const* d_in, const int* in_sizes, int n_in,
                              void* d_out, int out_size) {
    const float* in = (const float*)d_in[0];
    float* out = (float*)d_out;

    int total = in_sizes[0];           // 32 * 150528
    int D = total / B_ROWS;            // 150528
    int blocks = D / CHUNK_D;          // 588 (exact)

    ortho_tma_kernel<<<blocks, THREADS>>>(in, out, D, 1.0 / (double)D);
}

// round 6
// speedup vs baseline: 1.2330x; 1.2330x over previous
#include <cuda_runtime.h>
#include <cuda_bf16.h>
#include <cstdint>

// Off-diagonal Gram sum via:
//   (1/D) sum_d [ (sum_b x2[b,d])^2 - sum_b x2[b,d]^2 ],  x2 = x*x.
//
// R6: best structure so far (147 CTAs x 256 thr, 16-deep staged LDG.128)
// plus packed f32x2 math (halves FMA-pipe issue count; ptxas never emits
// FFMA2 from C++) and a float warp reduction (5 SHFL vs 10 for doubles).

#define B_ROWS 32
#define THREADS 256
#define BATCH 16

__device__ double g_acc = 0.0;
__device__ unsigned int g_count = 0;

__device__ __forceinline__ unsigned long long pk2(float lo, float hi) {
    unsigned long long r;
    asm("mov.b64 %0, {%1, %2};" : "=l"(r) : "f"(lo), "f"(hi));
    return r;
}
__device__ __forceinline__ void upk2(unsigned long long v, float& lo, float& hi) {
    asm("mov.b64 {%0, %1}, %2;" : "=f"(lo), "=f"(hi) : "l"(v));
}
__device__ __forceinline__ unsigned long long mul2(unsigned long long a, unsigned long long b) {
    unsigned long long r;
    asm("mul.rn.f32x2 %0, %1, %2;" : "=l"(r) : "l"(a), "l"(b));
    return r;
}
__device__ __forceinline__ unsigned long long add2(unsigned long long a, unsigned long long b) {
    unsigned long long r;
    asm("add.rn.f32x2 %0, %1, %2;" : "=l"(r) : "l"(a), "l"(b));
    return r;
}
__device__ __forceinline__ unsigned long long fma2(unsigned long long a, unsigned long long b,
                                                   unsigned long long c) {
    unsigned long long r;
    asm("fma.rn.f32x2 %0, %1, %2, %3;" : "=l"(r) : "l"(a), "l"(b), "l"(c));
    return r;
}

__global__ void __launch_bounds__(THREADS, 1)
ortho_fused_kernel(const float4* __restrict__ in,
                   float* __restrict__ out,
                   int d4, double inv_d) {
    int idx = blockIdx.x * THREADS + threadIdx.x;   // grid covers d4 exactly

    // packed accumulators: s01=(s_x,s_y), s23=(s_z,s_w); same for t
    unsigned long long s01 = 0ull, s23 = 0ull, t01 = 0ull, t23 = 0ull;

    const float4* p = in + idx;
    #pragma unroll
    for (int grp = 0; grp < B_ROWS / BATCH; grp++) {
        // stage BATCH independent LDG.128 before consuming any
        float4 v[BATCH];
        #pragma unroll
        for (int j = 0; j < BATCH; j++)
            v[j] = p[(size_t)(grp * BATCH + j) * d4];

        #pragma unroll
        for (int j = 0; j < BATCH; j++) {
            unsigned long long v01 = pk2(v[j].x, v[j].y);
            unsigned long long v23 = pk2(v[j].z, v[j].w);
            unsigned long long a01 = mul2(v01, v01);
            unsigned long long a23 = mul2(v23, v23);
            s01 = add2(s01, a01);
            s23 = add2(s23, a23);
            t01 = fma2(a01, a01, t01);
            t23 = fma2(a23, a23, t23);
        }
    }

    float sx, sy, sz, sw, tx, ty, tz, tw;
    upk2(s01, sx, sy); upk2(s23, sz, sw);
    upk2(t01, tx, ty); upk2(t23, tz, tw);
    float c = (fmaf(sx, sx, -tx) + fmaf(sy, sy, -ty))
            + (fmaf(sz, sz, -tz) + fmaf(sw, sw, -tw));

    // float warp reduction
    #pragma unroll
    for (int off = 16; off > 0; off >>= 1)
        c += __shfl_xor_sync(0xFFFFFFFFu, c, off);

    __shared__ float warp_sums[THREADS / 32];
    int lane = threadIdx.x & 31;
    int wid  = threadIdx.x >> 5;
    if (lane == 0) warp_sums[wid] = c;
    __syncthreads();

    if (threadIdx.x == 0) {
        double blk = 0.0;
        #pragma unroll
        for (int w = 0; w < THREADS / 32; w++) blk += (double)warp_sums[w];
        atomicAdd(&g_acc, blk);
        __threadfence();
        unsigned int ticket = atomicAdd(&g_count, 1u);
        if (ticket == gridDim.x - 1) {
            out[0] = (float)(g_acc * inv_d);
            g_acc = 0.0;     // reset for next graph replay
            g_count = 0u;
        }
    }
}

extern "C" void kernel_launch(void* const* d_in, const int* in_sizes, int n_in,
                              void* d_out, int out_size) {
    const float4* in = (const float4*)d_in[0];
    float* out = (float*)d_out;

    int total = in_sizes[0];           // 32 * 150528
    int D = total / B_ROWS;            // 150528
    int d4 = D / 4;                    // 37632 = 147 * 256

    int blocks = d4 / THREADS;         // 147, exact
    ortho_fused_kernel<<<blocks, THREADS>>>(in, out, d4, 1.0 / (double)D);
}

// round 7
// speedup vs baseline: 1.2647x; 1.0257x over previous
#include <cuda_runtime.h>
#include <cuda_bf16.h>
#include <cstdint>

// Off-diagonal Gram sum via:
//   (1/D) sum_d [ (sum_b x2[b,d])^2 - sum_b x2[b,d]^2 ],  x2 = x*x.
//
// R7: joint occupancy x MLP test at fixed grid=147.
// 512 threads/CTA (16 warps/SM), b-dimension split 2-way: thread
// (c, h) stages 16 unpredicated LDG.128 for rows h*16..h*16+15 of
// column c. Column sums s recombined via an 8KB smem exchange
// (pair tid <-> tid+256); the x^4 term is additive, no exchange.
// Packed f32x2 math in the inner loop.

#define B_ROWS 32
#define THREADS 512
#define HALF_ROWS 16

__device__ double g_acc = 0.0;
__device__ unsigned int g_count = 0;

__device__ __forceinline__ unsigned long long pk2(float lo, float hi) {
    unsigned long long r;
    asm("mov.b64 %0, {%1, %2};" : "=l"(r) : "f"(lo), "f"(hi));
    return r;
}
__device__ __forceinline__ void upk2(unsigned long long v, float& lo, float& hi) {
    asm("mov.b64 {%0, %1}, %2;" : "=f"(lo), "=f"(hi) : "l"(v));
}
__device__ __forceinline__ unsigned long long mul2(unsigned long long a, unsigned long long b) {
    unsigned long long r;
    asm("mul.rn.f32x2 %0, %1, %2;" : "=l"(r) : "l"(a), "l"(b));
    return r;
}
__device__ __forceinline__ unsigned long long add2(unsigned long long a, unsigned long long b) {
    unsigned long long r;
    asm("add.rn.f32x2 %0, %1, %2;" : "=l"(r) : "l"(a), "l"(b));
    return r;
}
__device__ __forceinline__ unsigned long long fma2(unsigned long long a, unsigned long long b,
                                                   unsigned long long c) {
    unsigned long long r;
    asm("fma.rn.f32x2 %0, %1, %2, %3;" : "=l"(r) : "l"(a), "l"(b), "l"(c));
    return r;
}

__global__ void __launch_bounds__(THREADS, 1)
ortho_fused_kernel(const float4* __restrict__ in,
                   float* __restrict__ out,
                   int d4, double inv_d) {
    const int tid = threadIdx.x;
    const int c   = tid & 255;          // column slot within CTA
    const int h   = tid >> 8;           // b-half: 0 or 1
    const int col = blockIdx.x * 256 + c;   // grid covers d4 exactly

    // 16 unpredicated staged loads: rows h*16 .. h*16+15 of column `col`
    const float4* p = in + (size_t)(h * HALF_ROWS) * d4 + col;
    float4 v[HALF_ROWS];
    #pragma unroll
    for (int j = 0; j < HALF_ROWS; j++)
        v[j] = p[(size_t)j * d4];

    unsigned long long s01 = 0ull, s23 = 0ull, t01 = 0ull, t23 = 0ull;
    #pragma unroll
    for (int j = 0; j < HALF_ROWS; j++) {
        unsigned long long v01 = pk2(v[j].x, v[j].y);
        unsigned long long v23 = pk2(v[j].z, v[j].w);
        unsigned long long a01 = mul2(v01, v01);
        unsigned long long a23 = mul2(v23, v23);
        s01 = add2(s01, a01);
        s23 = add2(s23, a23);
        t01 = fma2(a01, a01, t01);
        t23 = fma2(a23, a23, t23);
    }

    float sx, sy, sz, sw, tx, ty, tz, tw;
    upk2(s01, sx, sy); upk2(s23, sz, sw);
    upk2(t01, tx, ty); upk2(t23, tz, tw);
    float tsum = (tx + ty) + (tz + tw);

    // exchange partial s between the two b-halves of each column
    __shared__ float4 spart[THREADS];
    spart[tid] = make_float4(sx, sy, sz, sw);
    __syncthreads();

    float val = -tsum;
    if (h == 0) {
        float4 o = spart[tid + 256];
        float fx = sx + o.x, fy = sy + o.y, fz = sz + o.z, fw = sw + o.w;
        val += (fx * fx + fy * fy) + (fz * fz + fw * fw);
    }

    // float warp reduction
    #pragma unroll
    for (int off = 16; off > 0; off >>= 1)
        val += __shfl_xor_sync(0xFFFFFFFFu, val, off);

    __shared__ float warp_sums[THREADS / 32];
    int lane = tid & 31;
    int wid  = tid >> 5;
    if (lane == 0) warp_sums[wid] = val;
    __syncthreads();

    if (tid == 0) {
        double blk = 0.0;
        #pragma unroll
        for (int w = 0; w < THREADS / 32; w++) blk += (double)warp_sums[w];
        atomicAdd(&g_acc, blk);
        __threadfence();
        unsigned int ticket = atomicAdd(&g_count, 1u);
        if (ticket == gridDim.x - 1) {
            out[0] = (float)(g_acc * inv_d);
            g_acc = 0.0;     // reset for next graph replay
            g_count = 0u;
        }
    }
}

extern "C" void kernel_launch(void* const* d_in, const int* in_sizes, int n_in,
                              void* d_out, int out_size) {
    const float4* in = (const float4*)d_in[0];
    float* out = (float*)d_out;

    int total = in_sizes[0];           // 32 * 150528
    int D = total / B_ROWS;            // 150528
    int d4 = D / 4;                    // 37632 = 147 * 256

    int blocks = d4 / 256;             // 147, exact; 512 threads per CTA
    ortho_fused_kernel<<<blocks, THREADS>>>(in, out, d4, 1.0 / (double)D);
}